// round 1
// baseline (speedup 1.0000x reference)
#include <cuda_runtime.h>
#include <stdint.h>
#include <math.h>

// Problem constants
#define IMG_H 512
#define IMG_W 512
#define NIMG  128          // 8*16
#define NWARP 16           // 512 threads / 32
#define PIX_PER_IMG (IMG_H * IMG_W)
#define TOTAL_COUNTS 1048576.0f   // 4 * 512 * 512 = 2^20 (exact)

// Shared memory layout (dynamic):
//   [0, 131072)             per-lane u8 histograms: 16 warps * (64 word-rows * 128 B)
//   [131072, 147456)        per-warp u32 histograms: 16 * 256 * 4
//   [147456, 148480)        reduction scratch: 256 floats
#define HISTU8_BYTES (NWARP * 8192)
#define WHIST_BYTES  (NWARP * 256 * 4)
#define RED_BYTES    (256 * 4)
#define SMEM_BYTES   (HISTU8_BYTES + WHIST_BYTES + RED_BYTES)

__device__ float g_ent[NIMG];

__device__ __forceinline__ int quant(float v) {
    // matches (img * 15).astype(int32): truncation toward zero, plain fp32 mul
    return (int)(v * 15.0f);
}

__global__ __launch_bounds__(512, 1)
void glcm_hist_kernel(const float* __restrict__ x) {
    extern __shared__ unsigned char smem[];
    uint8_t*  histu8 = smem;
    uint32_t* whist  = (uint32_t*)(smem + HISTU8_BYTES);
    float*    red    = (float*)(smem + HISTU8_BYTES + WHIST_BYTES);

    const int tid  = threadIdx.x;
    const int warp = tid >> 5;
    const int lane = tid & 31;
    const int img  = blockIdx.x;
    const float* base = x + (size_t)img * PIX_PER_IMG;

    // ---- zero-init histograms ----
    {
        uint32_t* h32 = (uint32_t*)histu8;
        #pragma unroll
        for (int i = tid; i < HISTU8_BYTES / 4; i += 512) h32[i] = 0u;
        for (int i = tid; i < NWARP * 256; i += 512)      whist[i] = 0u;
    }
    __syncthreads();

    // Each thread owns column c. Warp-local halos avoid all cross-warp comm.
    const int c  = tid;
    const int cl = (c - 1) & (IMG_W - 1);
    const int cr = (c + 1) & (IMG_W - 1);

    // per-lane u8 hist base: bank == lane always (conflict-free)
    uint32_t* myhist = (uint32_t*)(histu8 + warp * 8192) + lane;

    // ---- preload "previous row" = row H-1 (wraparound) ----
    int qprev   = quant(base[(IMG_H - 1) * IMG_W + c]);
    int qprev_l = 0, qprev_r = 0;
    if (lane == 0)  qprev_l = quant(base[(IMG_H - 1) * IMG_W + cl]);
    if (lane == 31) qprev_r = quant(base[(IMG_H - 1) * IMG_W + cr]);

    for (int r = 0; r < IMG_H; r++) {
        const float xc = base[r * IMG_W + c];
        const int q = quant(xc);

        // halo quantized values for this row (needed now for s0, and as next qprev halos)
        int qcl_cur = 0, qcr_cur = 0;
        if (lane == 0)  qcl_cur = quant(base[r * IMG_W + cl]);
        if (lane == 31) qcr_cur = quant(base[r * IMG_W + cr]);

        // neighbor gray levels via warp shuffles (+halo fixups at warp edges)
        int s0   = __shfl_up_sync(0xFFFFFFFFu, q, 1);      // q[r][c-1]
        if (lane == 0)  s0 = qcl_cur;
        int s90  = qprev;                                   // q[r-1][c]
        int s135 = __shfl_up_sync(0xFFFFFFFFu, qprev, 1);   // q[r-1][c-1]
        if (lane == 0)  s135 = qprev_l;
        int s45  = __shfl_down_sync(0xFFFFFFFFu, qprev, 1); // q[r-1][c+1]
        if (lane == 31) s45 = qprev_r;

        // Build 16-byte increment vector over bins q*16 + s (s in 0..15).
        // lo covers s 0..7, hi covers s 8..15; duplicate s values merge automatically.
        unsigned long long lo = 0ull, hi = 0ull;
        {
            unsigned long long v;
            v = 1ull << ((s0   & 7) * 8); if (s0   < 8) lo += v; else hi += v;
            v = 1ull << ((s45  & 7) * 8); if (s45  < 8) lo += v; else hi += v;
            v = 1ull << ((s90  & 7) * 8); if (s90  < 8) lo += v; else hi += v;
            v = 1ull << ((s135 & 7) * 8); if (s135 < 8) lo += v; else hi += v;
        }
        const uint32_t i0 = (uint32_t)lo, i1 = (uint32_t)(lo >> 32);
        const uint32_t i2 = (uint32_t)hi, i3 = (uint32_t)(hi >> 32);

        // RMW the 4 words of bin-group q (distinct addresses, bank == lane)
        uint32_t* hw = myhist + q * 128;
        hw[0]  += i0;
        hw[32] += i1;
        hw[64] += i2;
        hw[96] += i3;

        qprev   = q;
        qprev_l = qcl_cur;
        qprev_r = qcr_cur;

        // ---- warp-local flush every 32 rows (max 128 per u8 bin, no overflow) ----
        if ((r & 31) == 31) {
            #pragma unroll 4
            for (int wr = 0; wr < 64; wr++) {
                uint32_t* p = (uint32_t*)(histu8 + warp * 8192 + wr * 128) + lane;
                uint32_t wv = *p;
                *p = 0u;
                uint32_t se = __reduce_add_sync(0xFFFFFFFFu, wv & 0x00FF00FFu);
                uint32_t so = __reduce_add_sync(0xFFFFFFFFu, (wv >> 8) & 0x00FF00FFu);
                if (lane < 4) {
                    uint32_t add = (lane == 0) ? (se & 0xFFFFu)
                                 : (lane == 1) ? (so & 0xFFFFu)
                                 : (lane == 2) ? (se >> 16)
                                               : (so >> 16);
                    whist[warp * 256 + wr * 4 + lane] += add;
                }
            }
        }
    }

    __syncthreads();

    // ---- reduce 16 warp histograms -> entropy ----
    if (tid < 256) {
        uint32_t cnt = 0;
        #pragma unroll
        for (int w = 0; w < NWARP; w++) cnt += whist[w * 256 + tid];
        const float p = (float)cnt * (1.0f / TOTAL_COUNTS);  // exact: /2^20
        red[tid] = -p * logf(p + 1e-10f);
    }
    __syncthreads();
    if (tid < 128) red[tid] += red[tid + 128];
    __syncthreads();
    if (tid < 64)  red[tid] += red[tid + 64];
    __syncthreads();
    if (tid < 32) {
        float v = red[tid] + red[tid + 32];
        #pragma unroll
        for (int o = 16; o > 0; o >>= 1) v += __shfl_down_sync(0xFFFFFFFFu, v, o);
        if (tid == 0) g_ent[img] = v;
    }
}

// Broadcast each image's entropy scalar across its (H,W) output slice, float4 stores.
__global__ void fill_kernel(float4* __restrict__ out, int n4) {
    const unsigned i = blockIdx.x * blockDim.x + threadIdx.x;
    if (i >= (unsigned)n4) return;
    const int img = i >> 16;  // 512*512/4 = 65536 float4 per image
    const float v = g_ent[img];
    out[i] = make_float4(v, v, v, v);
}

extern "C" void kernel_launch(void* const* d_in, const int* in_sizes, int n_in,
                              void* d_out, int out_size) {
    const float* x = (const float*)d_in[0];
    float4* out4 = (float4*)d_out;

    cudaFuncSetAttribute(glcm_hist_kernel,
                         cudaFuncAttributeMaxDynamicSharedMemorySize, SMEM_BYTES);

    glcm_hist_kernel<<<NIMG, 512, SMEM_BYTES>>>(x);

    const int n4 = out_size / 4;
    const int blocks = (n4 + 255) / 256;
    fill_kernel<<<blocks, 256>>>(out4, n4);
}

// round 2
// speedup vs baseline: 3.0800x; 3.0800x over previous
#include <cuda_runtime.h>
#include <stdint.h>
#include <math.h>

#define NIMG 128
#define IMG_H 512
#define IMG_W 512
#define PIX (IMG_H * IMG_W)

// Global scratch (static __device__ arrays: allowed, no allocation)
__device__ uint32_t g_q[NIMG * PIX / 4];   // packed quantized bytes (33.5 MB)
__device__ uint32_t g_hist[NIMG * 256];    // per-image 256-bin u32 histograms
__device__ float    g_ent[NIMG];

// ---------------- K1: quantize + pack, zero g_hist ----------------
__global__ __launch_bounds__(256)
void quant_kernel(const float4* __restrict__ x) {
    const unsigned gid = blockIdx.x * 256u + threadIdx.x;   // exactly NIMG*PIX/4 threads
    if (gid < NIMG * 256) g_hist[gid] = 0u;                 // zero hist scratch (first 128 blocks)
    const float4 v = x[gid];
    uint32_t b0 = (uint32_t)(int)(v.x * 15.0f);
    uint32_t b1 = (uint32_t)(int)(v.y * 15.0f);
    uint32_t b2 = (uint32_t)(int)(v.z * 15.0f);
    uint32_t b3 = (uint32_t)(int)(v.w * 15.0f);
    g_q[gid] = b0 | (b1 << 8) | (b2 << 16) | (b3 << 24);
}

// ---------------- K2: GLCM histogram ----------------
// grid = 1024 (img*8 + band), 256 threads = 8 warps.
// Warp w: quarter Qc = w&3 (128 cols), half = w>>2 (32 rows of the 64-row band).
// Lane handles 4 adjacent pixels per row via one u32 of packed bytes.
// Per-lane byte histograms: row q = 2 u64 (16 byte-bins), lane-strided (bank-clean).

__device__ __forceinline__ unsigned long long shl64(uint32_t k) {
    // PTX shl.b64 clamps: shift >= 64 (incl. negative-as-unsigned) -> 0.
    unsigned long long r;
    asm("shl.b64 %0, 1, %1;" : "=l"(r) : "r"(k));
    return r;
}

__device__ __forceinline__ void warp_flush(unsigned long long* wb, int lane, uint32_t* gh) {
    #pragma unroll 4
    for (int p = 0; p < 32; p++) {
        unsigned long long v = wb[p * 32 + lane];
        wb[p * 32 + lane] = 0ull;
        uint32_t w0 = (uint32_t)v, w1 = (uint32_t)(v >> 32);
        uint32_t se0 = __reduce_add_sync(0xFFFFFFFFu,  w0        & 0x00FF00FFu);
        uint32_t so0 = __reduce_add_sync(0xFFFFFFFFu, (w0 >> 8)  & 0x00FF00FFu);
        uint32_t se1 = __reduce_add_sync(0xFFFFFFFFu,  w1        & 0x00FF00FFu);
        uint32_t so1 = __reduce_add_sync(0xFFFFFFFFu, (w1 >> 8)  & 0x00FF00FFu);
        if (lane < 8) {
            uint32_t se = (lane & 4) ? se1 : se0;
            uint32_t so = (lane & 4) ? so1 : so0;
            uint32_t vv = (lane & 1) ? so  : se;
            uint32_t add = (lane & 2) ? (vv >> 16) : (vv & 0xFFFFu);
            if (add) atomicAdd(gh + p * 8 + lane, add);
        }
    }
}

__global__ __launch_bounds__(256)
void hist_kernel() {
    extern __shared__ unsigned long long hist[];   // 8 warps * 1024 u64 = 64 KB
    const int tid  = threadIdx.x;
    const int warp = tid >> 5;
    const int lane = tid & 31;
    const int img  = blockIdx.x >> 3;
    const int band = blockIdx.x & 7;

    for (int i = tid; i < 8 * 1024; i += 256) hist[i] = 0ull;
    __syncthreads();

    const int Qc   = warp & 3;
    const int half = warp >> 2;
    const int r0   = band * 64 + half * 32;

    const uint32_t* __restrict__ qrow = g_q + (size_t)img * (PIX / 4);
    const uint8_t*  __restrict__ qb8  = (const uint8_t*)qrow;
    uint32_t* gh = g_hist + img * 256;

    const int widx = Qc * 32 + lane;                 // u32 word index within row (128/row)
    const int lcol = (Qc * 128 - 1) & (IMG_W - 1);   // left halo column
    const int rcol = (Qc * 128 + 128) & (IMG_W - 1); // right halo column
    const bool l0  = (lane == 0);
    const bool l31 = (lane == 31);

    unsigned long long* wb = hist + warp * 1024;

    // ---- preload row above (wraps) and row r0 ----
    const int ga = (r0 - 1) & (IMG_H - 1);
    uint32_t above = qrow[ga * 128 + widx];
    uint32_t al_b  = l0  ? (uint32_t)qb8[ga * IMG_W + lcol] : 0u;
    uint32_t ar_b  = l31 ? (uint32_t)qb8[ga * IMG_W + rcol] : 0u;
    uint32_t t;
    t = __shfl_up_sync(0xFFFFFFFFu, above, 1);
    uint32_t al = l0 ? (al_b << 24) : t;             // above-left word (only byte3 used)
    t = __shfl_down_sync(0xFFFFFFFFu, above, 1);
    uint32_t ar = l31 ? ar_b : t;                    // above-right word (only byte0 used)

    uint32_t cur = qrow[r0 * 128 + widx];
    uint32_t lh  = l0  ? (uint32_t)qb8[r0 * IMG_W + lcol] : 0u;
    uint32_t rh  = l31 ? (uint32_t)qb8[r0 * IMG_W + rcol] : 0u;

    for (int i = 0; i < 32; i++) {
        const int gr = r0 + i;
        // prefetch next row (breaks LDG out of the dependence chain)
        uint32_t ncur = 0, nlh = 0, nrh = 0;
        if (i < 31) {
            ncur = qrow[(gr + 1) * 128 + widx];
            nlh  = l0  ? (uint32_t)qb8[(gr + 1) * IMG_W + lcol] : 0u;
            nrh  = l31 ? (uint32_t)qb8[(gr + 1) * IMG_W + rcol] : 0u;
        }

        t = __shfl_up_sync(0xFFFFFFFFu, cur, 1);
        const uint32_t cl = l0 ? (lh << 24) : t;

        const uint32_t s0w   = __byte_perm(cur,   cl, 0x2107);  // q[i][j-1]
        const uint32_t s45w  = __byte_perm(above, ar, 0x4321);  // q[i-1][j+1]
        const uint32_t s90w  = above;                           // q[i-1][j]
        const uint32_t s135w = __byte_perm(above, al, 0x2107);  // q[i-1][j-1]

        #pragma unroll
        for (int k = 0; k < 4; k++) {
            const uint32_t q = __byte_perm(cur, 0, 0x4440 | k);
            const uint32_t k0 = __byte_perm(s0w,   0, 0x4440 | k) << 3;
            const uint32_t k1 = __byte_perm(s45w,  0, 0x4440 | k) << 3;
            const uint32_t k2 = __byte_perm(s90w,  0, 0x4440 | k) << 3;
            const uint32_t k3 = __byte_perm(s135w, 0, 0x4440 | k) << 3;
            // 16-byte one-hot-sum, split as two u64; shl clamps make the split branch-free
            unsigned long long lo = shl64(k0) + shl64(k1) + shl64(k2) + shl64(k3);
            unsigned long long hi = shl64(k0 - 64u) + shl64(k1 - 64u) +
                                    shl64(k2 - 64u) + shl64(k3 - 64u);
            unsigned long long* hb = wb + q * 64 + lane;  // bank-clean: q*512B ≡ 0 mod 128B
            hb[0]  += lo;   // bins q*16 + 0..7
            hb[32] += hi;   // bins q*16 + 8..15
        }

        // rotate row state
        above = cur;
        al = cl;
        t = __shfl_down_sync(0xFFFFFFFFu, cur, 1);
        ar = l31 ? rh : t;
        cur = ncur; lh = nlh; rh = nrh;

        // flush before byte overflow (worst case 16/row/byte -> 15 rows = 240 <= 255)
        if (i == 14 || i == 29 || i == 31) warp_flush(wb, lane, gh);
    }
}

// ---------------- K3: entropy per image ----------------
__global__ __launch_bounds__(256)
void entropy_kernel() {
    __shared__ float red[256];
    const int img = blockIdx.x, t = threadIdx.x;
    const float p = (float)g_hist[img * 256 + t] * (1.0f / 1048576.0f);
    red[t] = -p * logf(p + 1e-10f);
    __syncthreads();
    if (t < 128) red[t] += red[t + 128];
    __syncthreads();
    if (t < 64)  red[t] += red[t + 64];
    __syncthreads();
    if (t < 32) {
        float v = red[t] + red[t + 32];
        #pragma unroll
        for (int o = 16; o > 0; o >>= 1) v += __shfl_down_sync(0xFFFFFFFFu, v, o);
        if (t == 0) g_ent[img] = v;
    }
}

// ---------------- K4: broadcast fill ----------------
__global__ void fill_kernel(float4* __restrict__ out, int n4) {
    const unsigned i = blockIdx.x * blockDim.x + threadIdx.x;
    if (i >= (unsigned)n4) return;
    const int img = i >> 16;    // 65536 float4 per image slice
    const float v = g_ent[img];
    out[i] = make_float4(v, v, v, v);
}

extern "C" void kernel_launch(void* const* d_in, const int* in_sizes, int n_in,
                              void* d_out, int out_size) {
    const float4* x = (const float4*)d_in[0];
    float4* out4 = (float4*)d_out;

    cudaFuncSetAttribute(hist_kernel, cudaFuncAttributeMaxDynamicSharedMemorySize, 65536);

    quant_kernel<<<NIMG * PIX / 4 / 256, 256>>>(x);          // 32768 blocks
    hist_kernel<<<NIMG * 8, 256, 65536>>>();                 // 1024 blocks
    entropy_kernel<<<NIMG, 256>>>();
    const int n4 = out_size / 4;
    fill_kernel<<<(n4 + 255) / 256, 256>>>(out4, n4);
}

// round 4
// speedup vs baseline: 3.0963x; 1.0053x over previous
#include <cuda_runtime.h>
#include <stdint.h>
#include <math.h>

#define NIMG 128
#define IMG_H 512
#define IMG_W 512
#define PIX (IMG_H * IMG_W)

__device__ uint32_t g_hist[NIMG * 256];   // zero-initialized at module load; re-zeroed by entropy_kernel
__device__ float    g_ent[NIMG];

// ---- quantize 4 floats -> packed bytes (matches (x*15).astype(int32) truncation) ----
__device__ __forceinline__ uint32_t qpack(float4 v) {
    uint32_t b0 = (uint32_t)(int)(v.x * 15.0f);
    uint32_t b1 = (uint32_t)(int)(v.y * 15.0f);
    uint32_t b2 = (uint32_t)(int)(v.z * 15.0f);
    uint32_t b3 = (uint32_t)(int)(v.w * 15.0f);
    return b0 | (b1 << 8) | (b2 << 16) | (b3 << 24);
}
__device__ __forceinline__ uint32_t qbyte(float v) {
    return (uint32_t)(int)(v * 15.0f);
}

__device__ __forceinline__ unsigned long long shl64(uint32_t k) {
    // PTX shl.b64 clamps: shift >= 64 (incl. negative-as-unsigned) -> 0
    unsigned long long r;
    asm("shl.b64 %0, 1, %1;" : "=l"(r) : "r"(k));
    return r;
}

__device__ __forceinline__ void warp_flush(unsigned long long* wb, int lane, uint32_t* gh) {
    #pragma unroll 4
    for (int p = 0; p < 32; p++) {
        unsigned long long v = wb[p * 32 + lane];
        wb[p * 32 + lane] = 0ull;
        uint32_t w0 = (uint32_t)v, w1 = (uint32_t)(v >> 32);
        uint32_t se0 = __reduce_add_sync(0xFFFFFFFFu,  w0        & 0x00FF00FFu);
        uint32_t so0 = __reduce_add_sync(0xFFFFFFFFu, (w0 >> 8)  & 0x00FF00FFu);
        uint32_t se1 = __reduce_add_sync(0xFFFFFFFFu,  w1        & 0x00FF00FFu);
        uint32_t so1 = __reduce_add_sync(0xFFFFFFFFu, (w1 >> 8)  & 0x00FF00FFu);
        if (lane < 8) {
            uint32_t se = (lane & 4) ? se1 : se0;
            uint32_t so = (lane & 4) ? so1 : so0;
            uint32_t vv = (lane & 1) ? so  : se;
            uint32_t add = (lane & 2) ? (vv >> 16) : (vv & 0xFFFFu);
            if (add) atomicAdd(gh + p * 8 + lane, add);
        }
    }
}

// ---------------- fused quantize + GLCM histogram ----------------
// grid = 2048 (img*16 + band), 128 threads = 4 warps, 32 KB smem -> 7 CTAs/SM.
// Warp w owns cols [w*128, w*128+128) of a 32-row band; lane handles 4 cols/row.
__global__ __launch_bounds__(128)
void hist_kernel(const float4* __restrict__ x) {
    extern __shared__ unsigned long long hist[];   // 4 warps * 1024 u64 = 32 KB
    const int tid  = threadIdx.x;
    const int warp = tid >> 5;
    const int lane = tid & 31;
    const int img  = blockIdx.x >> 4;
    const int band = blockIdx.x & 15;

    #pragma unroll
    for (int i = tid; i < 4 * 1024; i += 128) hist[i] = 0ull;
    __syncthreads();

    const int r0 = band * 32;
    const float4* __restrict__ imgb = x + (size_t)img * (PIX / 4);
    const float*  __restrict__ imgf = (const float*)imgb;
    uint32_t* gh = g_hist + img * 256;

    const int widx = warp * 32 + lane;                 // float4 index within row (128/row)
    const int lcol = (warp * 128 - 1) & (IMG_W - 1);   // left halo column
    const int rcol = (warp * 128 + 128) & (IMG_W - 1); // right halo column
    const bool l0  = (lane == 0);
    const bool l31 = (lane == 31);

    unsigned long long* wb = hist + warp * 1024;

    // ---- preload row above (wraps) and row r0, quantized+packed ----
    const int ga = (r0 - 1) & (IMG_H - 1);
    uint32_t above = qpack(imgb[ga * 128 + widx]);
    uint32_t al_b  = l0  ? qbyte(imgf[ga * IMG_W + lcol]) : 0u;
    uint32_t ar_b  = l31 ? qbyte(imgf[ga * IMG_W + rcol]) : 0u;
    uint32_t t;
    t = __shfl_up_sync(0xFFFFFFFFu, above, 1);
    uint32_t al = l0 ? (al_b << 24) : t;               // above-left (only byte3 used)
    t = __shfl_down_sync(0xFFFFFFFFu, above, 1);
    uint32_t ar = l31 ? ar_b : t;                      // above-right (only byte0 used)

    uint32_t cur = qpack(imgb[r0 * 128 + widx]);
    uint32_t lh  = l0  ? qbyte(imgf[r0 * IMG_W + lcol]) : 0u;
    uint32_t rh  = l31 ? qbyte(imgf[r0 * IMG_W + rcol]) : 0u;

    for (int i = 0; i < 32; i++) {
        const int gr = r0 + i;
        // prefetch next row's floats (LDG.128 out of the dependence chain)
        float4 nf = make_float4(0.f, 0.f, 0.f, 0.f);
        float nlf = 0.f, nrf = 0.f;
        if (i < 31) {
            nf = imgb[(gr + 1) * 128 + widx];
            if (l0)  nlf = imgf[(gr + 1) * IMG_W + lcol];
            if (l31) nrf = imgf[(gr + 1) * IMG_W + rcol];
        }

        t = __shfl_up_sync(0xFFFFFFFFu, cur, 1);
        const uint32_t cl = l0 ? (lh << 24) : t;

        const uint32_t s0w   = __byte_perm(cur,   cl, 0x2107);  // q[i][j-1]
        const uint32_t s45w  = __byte_perm(above, ar, 0x4321);  // q[i-1][j+1]
        const uint32_t s90w  = above;                           // q[i-1][j]
        const uint32_t s135w = __byte_perm(above, al, 0x2107);  // q[i-1][j-1]

        #pragma unroll
        for (int k = 0; k < 4; k++) {
            const uint32_t q  = __byte_perm(cur, 0, 0x4440 | k);
            const uint32_t k0 = __byte_perm(s0w,   0, 0x4440 | k) << 3;
            const uint32_t k1 = __byte_perm(s45w,  0, 0x4440 | k) << 3;
            const uint32_t k2 = __byte_perm(s90w,  0, 0x4440 | k) << 3;
            const uint32_t k3 = __byte_perm(s135w, 0, 0x4440 | k) << 3;
            unsigned long long lo = shl64(k0) + shl64(k1) + shl64(k2) + shl64(k3);
            unsigned long long hi = shl64(k0 - 64u) + shl64(k1 - 64u) +
                                    shl64(k2 - 64u) + shl64(k3 - 64u);
            unsigned long long* hb = wb + q * 64 + lane;  // bank-clean: q*512B ≡ 0 mod 128B
            hb[0]  += lo;   // bins q*16 + 0..7
            hb[32] += hi;   // bins q*16 + 8..15
        }

        // rotate row state
        above = cur;
        al = cl;
        t = __shfl_down_sync(0xFFFFFFFFu, cur, 1);
        ar = l31 ? rh : t;
        cur = qpack(nf);
        lh  = qbyte(nlf);
        rh  = qbyte(nrf);

        // flush before byte overflow (worst case 16/row/byte -> 15 rows = 240 <= 255)
        if (i == 14 || i == 29 || i == 31) warp_flush(wb, lane, gh);
    }
}

// ---------------- entropy per image (+ re-zero g_hist for next replay) ----------------
__global__ __launch_bounds__(256)
void entropy_kernel() {
    __shared__ float red[256];
    const int img = blockIdx.x, t = threadIdx.x;
    const uint32_t cnt = g_hist[img * 256 + t];
    g_hist[img * 256 + t] = 0u;              // keeps every graph replay starting from zeros
    const float p = (float)cnt * (1.0f / 1048576.0f);
    red[t] = -p * logf(p + 1e-10f);
    __syncthreads();
    if (t < 128) red[t] += red[t + 128];
    __syncthreads();
    if (t < 64)  red[t] += red[t + 64];
    __syncthreads();
    if (t < 32) {
        float v = red[t] + red[t + 32];
        #pragma unroll
        for (int o = 16; o > 0; o >>= 1) v += __shfl_down_sync(0xFFFFFFFFu, v, o);
        if (t == 0) g_ent[img] = v;
    }
}

// ---------------- broadcast fill: 2x float4 streaming stores per thread ----------------
__global__ __launch_bounds__(256)
void fill_kernel(float4* __restrict__ out) {
    const unsigned i = (blockIdx.x * 256u + threadIdx.x) * 2u;  // even-aligned pair
    const int img = i >> 16;                                    // 65536 float4 per image
    const float v = g_ent[img];
    const float4 f = make_float4(v, v, v, v);
    __stcs(out + i,     f);
    __stcs(out + i + 1, f);   // 65536 is even: pair never straddles an image boundary
}

extern "C" void kernel_launch(void* const* d_in, const int* in_sizes, int n_in,
                              void* d_out, int out_size) {
    const float4* x = (const float4*)d_in[0];
    float4* out4 = (float4*)d_out;

    cudaFuncSetAttribute(hist_kernel, cudaFuncAttributeMaxDynamicSharedMemorySize, 32768);

    hist_kernel<<<NIMG * 16, 128, 32768>>>(x);     // 2048 CTAs, ~1.98 waves at 7 CTAs/SM
    entropy_kernel<<<NIMG, 256>>>();
    const int n4 = out_size / 4;                   // 8388608
    fill_kernel<<<n4 / (256 * 2), 256>>>(out4);    // 16384 blocks
}